// round 7
// baseline (speedup 1.0000x reference)
#include <cuda_runtime.h>
#include <cuda_fp16.h>

// ---------------------------------------------------------------------------
// LaplacianPyramid. Gather = 2 scattered LDG.64/pixel from fp16 footprint
// tables (67 MB, L2-resident), at the L1tex wavefront floor.
// R7: pack1 vectorized (float4 + shfl_up for the left neighbor), gather at
// 4 px/thread with batched loads.
// ---------------------------------------------------------------------------

struct alignas(8) H4 {
    __half2 t;  // (v00, v01)
    __half2 b;  // (v10, v11)
};

__device__ H4    g_P1h[2049 * 2049];   // layer1 footprints      (33.6 MB)
__device__ H4    g_PCh[2048 * 2048];   // combined footprints    (33.5 MB)
__device__ float g_C  [2049 * 2049];   // combined knots, fp32   (16.8 MB)
__device__ float g_H2 [1024 * 2049];   // horizontal pass, S=1024
__device__ float g_H3 [ 512 * 2049];   // S=512
__device__ float g_H4 [ 256 * 2049];   // S=256

template <int S>
__device__ __forceinline__ float* hbuf() {
    if constexpr (S == 1024) return g_H2;
    else if constexpr (S == 512) return g_H3;
    else return g_H4;
}

// ---- layer1 footprint pack: 4 entries/thread, float4 loads + shfl ----
// Output entry (yi, xi) = 2x2 of src at rows yi-1, yi and cols xi-1, xi
// (zero outside). Thread t covers xi = 4t .. 4t+3.
__global__ void __launch_bounds__(128) pack1_kernel(const float* __restrict__ src) {
    const int S = 2048;
    int t = blockIdx.x * blockDim.x + threadIdx.x;
    int x4 = t * 4;                      // 0,4,...,2048 (t<=512 active)
    int yi = blockIdx.y;                 // [0, 2048]
    bool active = (x4 <= S);

    bool r0v = (yi >= 1);                // src row yi-1 exists
    bool r1v = (yi <= S - 1);            // src row yi   exists
    const float* row0 = src + (long long)(yi - 1) * S;
    const float* row1 = src + (long long)yi * S;

    float4 a0 = make_float4(0.f, 0.f, 0.f, 0.f);
    float4 a1 = make_float4(0.f, 0.f, 0.f, 0.f);
    // x4 multiples of 4: either fully in-range (x4<=2044) or fully out (2048).
    if (active && x4 + 3 <= S - 1) {
        if (r0v) a0 = *reinterpret_cast<const float4*>(row0 + x4);
        if (r1v) a1 = *reinterpret_cast<const float4*>(row1 + x4);
    }
    // left neighbor col x4-1 from previous lane's a.w
    float l0 = __shfl_up_sync(0xffffffffu, a0.w, 1);
    float l1 = __shfl_up_sync(0xffffffffu, a1.w, 1);
    if ((threadIdx.x & 31) == 0) {
        int c = x4 - 1;
        l0 = (r0v && c >= 0) ? __ldg(row0 + c) : 0.f;
        l1 = (r1v && c >= 0) ? __ldg(row1 + c) : 0.f;
    }
    if (!active) return;

    float v0[5] = {l0, a0.x, a0.y, a0.z, a0.w};
    float v1[5] = {l1, a1.x, a1.y, a1.z, a1.w};
    H4* dst = g_P1h + yi * (S + 1) + x4;
    if (x4 + 3 <= S) {
#pragma unroll
        for (int k = 0; k < 4; k++) {
            H4 h;
            h.t = __floats2half2_rn(v0[k], v0[k + 1]);
            h.b = __floats2half2_rn(v1[k], v1[k + 1]);
            dst[k] = h;  // 8B stores (2049-stride rows are only 8B-aligned)
        }
    } else {  // x4 == 2048: single entry
        H4 h;
        h.t = __floats2half2_rn(v0[0], 0.f);
        h.b = __floats2half2_rn(v1[0], 0.f);
        dst[0] = h;
    }
}

// ---- horizontal resample of layer S onto the 2048-knot x-grid ----
template <int S>
__global__ void __launch_bounds__(256) hpass_kernel(const float* __restrict__ src) {
    int m = blockIdx.x * blockDim.x + threadIdx.x;  // [0, 2048]
    int y = blockIdx.y;                             // [0, S)
    if (m > 2048) return;
    const float sc = (float)S / 2048.0f;
    float x = fmaf((float)m, sc, -0.5f);
    float xf = floorf(x);
    float wx = x - xf;
    int x0 = (int)xf;
    const float* r = src + (long long)y * S;
    float v0 = (x0 >= 0 && x0 < S) ? __ldg(r + x0) : 0.f;
    float v1 = (x0 + 1 >= 0 && x0 + 1 < S) ? __ldg(r + x0 + 1) : 0.f;
    hbuf<S>()[y * 2049 + m] = fmaf(wx, v1 - v0, v0);
}

// ---- vertical resample + sum over layers -> C knots ----
template <int S>
__device__ __forceinline__ float vtap(int m, int n) {
    const float sc = (float)S / 2048.0f;
    float y = fmaf((float)n, sc, -0.5f);
    float yf = floorf(y);
    float wy = y - yf;
    int y0 = (int)yf;
    const float* H = hbuf<S>();
    float v0 = (y0 >= 0 && y0 < S) ? __ldg(H + y0 * 2049 + m) : 0.f;
    float v1 = (y0 + 1 >= 0 && y0 + 1 < S) ? __ldg(H + (y0 + 1) * 2049 + m) : 0.f;
    return fmaf(wy, v1 - v0, v0);
}

__global__ void __launch_bounds__(256) vpass_kernel() {
    int m = blockIdx.x * blockDim.x + threadIdx.x;  // [0, 2048]
    int n = blockIdx.y;                             // [0, 2048]
    if (m > 2048) return;
    g_C[n * 2049 + m] = vtap<1024>(m, n) + vtap<512>(m, n) + vtap<256>(m, n);
}

// ---- combined footprint pack, 4 entries/thread, 16B vector stores ----
__global__ void __launch_bounds__(256) pack_c_kernel() {
    int m4 = (blockIdx.x * blockDim.x + threadIdx.x) * 4;  // [0, 2044]
    int n = blockIdx.y;                                    // [0, 2047]
    if (m4 >= 2048) return;
    const float* r0 = g_C + n * 2049 + m4;
    const float* r1 = r0 + 2049;
    float a[5], b[5];
#pragma unroll
    for (int k = 0; k < 5; k++) {
        a[k] = __ldg(r0 + k);
        b[k] = __ldg(r1 + k);
    }
    H4 e[4];
#pragma unroll
    for (int k = 0; k < 4; k++) {
        e[k].t = __floats2half2_rn(a[k], a[k + 1]);
        e[k].b = __floats2half2_rn(b[k], b[k + 1]);
    }
    float4* dst = reinterpret_cast<float4*>(g_PCh + n * 2048 + m4);
    dst[0] = *reinterpret_cast<float4*>(&e[0]);
    dst[1] = *reinterpret_cast<float4*>(&e[2]);
}

// ---- gather: 4 px/thread, batched index calc -> 8 loads -> math ----
__global__ void __launch_bounds__(256) gather_kernel(
    const float4* __restrict__ uv2, float4* __restrict__ out4, int nquad) {
    int i = blockIdx.x * blockDim.x + threadIdx.x;
    if (i >= nquad) return;
    float4 ga = __ldcs(uv2 + 2 * i);
    float4 gb = __ldcs(uv2 + 2 * i + 1);
    float u[4] = {ga.x, ga.z, gb.x, gb.z};
    float v[4] = {ga.y, ga.w, gb.y, gb.w};

    float x1[4], y1[4], xf1[4], yf1[4], xc[4], yc[4];
    int i1[4], ic[4], xic[4], yic[4];
#pragma unroll
    for (int p = 0; p < 4; p++) {
        x1[p] = fmaf(u[p], 2048.f, -0.5f);
        y1[p] = fmaf(v[p], 2048.f, -0.5f);
        xf1[p] = floorf(x1[p]);
        yf1[p] = floorf(y1[p]);
        int xi1 = max(0, min(2048, (int)xf1[p] + 1));
        int yi1 = max(0, min(2048, (int)yf1[p] + 1));
        i1[p] = yi1 * 2049 + xi1;
        xc[p] = u[p] * 2048.f;
        yc[p] = v[p] * 2048.f;
        xic[p] = min((int)xc[p], 2047);
        yic[p] = min((int)yc[p], 2047);
        ic[p] = yic[p] * 2048 + xic[p];
    }
    // issue all 8 scattered loads back-to-back
    H4 t1[4], tc[4];
#pragma unroll
    for (int p = 0; p < 4; p++) t1[p] = g_P1h[i1[p]];
#pragma unroll
    for (int p = 0; p < 4; p++) tc[p] = g_PCh[ic[p]];

    float r[4];
#pragma unroll
    for (int p = 0; p < 4; p++) {
        float wx1 = x1[p] - xf1[p], wy1 = y1[p] - yf1[p];
        float2 a_t = __half22float2(t1[p].t);
        float2 a_b = __half22float2(t1[p].b);
        float top1 = fmaf(wx1, a_t.y - a_t.x, a_t.x);
        float bot1 = fmaf(wx1, a_b.y - a_b.x, a_b.x);
        float a = fmaf(wy1, bot1 - top1, top1);

        float wxc = xc[p] - (float)xic[p], wyc = yc[p] - (float)yic[p];
        float2 c_t = __half22float2(tc[p].t);
        float2 c_b = __half22float2(tc[p].b);
        float topc = fmaf(wxc, c_t.y - c_t.x, c_t.x);
        float botc = fmaf(wxc, c_b.y - c_b.x, c_b.x);
        float b = fmaf(wyc, botc - topc, topc);
        r[p] = a + b;
    }
    __stcs(out4 + i, make_float4(r[0], r[1], r[2], r[3]));
}

extern "C" void kernel_launch(void* const* d_in, const int* in_sizes, int n_in,
                              void* d_out, int out_size) {
    const float* uv = (const float*)d_in[0];
    const float* l1 = (const float*)d_in[1];  // 2048 x 2048
    const float* l2 = (const float*)d_in[2];  // 1024 x 1024
    const float* l3 = (const float*)d_in[3];  // 512  x 512
    const float* l4 = (const float*)d_in[4];  // 256  x 256

    hpass_kernel<1024><<<dim3(9, 1024), 256>>>(l2);
    hpass_kernel<512><<<dim3(9, 512), 256>>>(l3);
    hpass_kernel<256><<<dim3(9, 256), 256>>>(l4);
    pack1_kernel<<<dim3((513 + 127) / 128, 2049), 128>>>(l1);
    vpass_kernel<<<dim3(9, 2049), 256>>>();
    pack_c_kernel<<<dim3(2, 2048), 256>>>();

    int nquad = out_size / 4;  // 8*1024*1024 / 4
    gather_kernel<<<(nquad + 255) / 256, 256>>>(
        (const float4*)uv, (float4*)d_out, nquad);
}